// round 13
// baseline (speedup 1.0000x reference)
#include <cuda_runtime.h>
#include <cstdint>

#define N_PDE   4096
#define WINDOW  327
#define HALF    163
#define TB      8                  // starts per phase-B block
#define NBLK_B  (N_PDE / TB)       // 512
#define HS      260                // hbuf stride (float4-aligned, conflict-free)
#define KSUB    4                  // table samples per xi-bin
#define NTAB    (N_PDE * KSUB)     // 16384 table entries
#define EPAD    384                // padded error buffer size (covers max tap)

// Scratch (allocation-free rule: __device__ globals)
__device__ float  g_R20[20 * 327];     // normalized resize rows
__device__ float  g_hc[N_PDE * 32];    // branch output folded through cW[:256] (+cb)
__device__ float2 g_tab[NTAB];         // (u,v) final outputs on the xi grid

// ---------------------------------------------------------------------------
// helpers
// ---------------------------------------------------------------------------
__device__ __forceinline__ float2 fma2(float2 a, float2 b, float2 c) {
    float2 d;
    asm("{\n\t"
        ".reg .b64 ra, rb, rc, rd;\n\t"
        "mov.b64 ra, {%2,%3};\n\t"
        "mov.b64 rb, {%4,%5};\n\t"
        "mov.b64 rc, {%6,%7};\n\t"
        "fma.rn.f32x2 rd, ra, rb, rc;\n\t"
        "mov.b64 {%0,%1}, rd;\n\t"
        "}"
        : "=f"(d.x), "=f"(d.y)
        : "f"(a.x), "f"(a.y), "f"(b.x), "f"(b.y), "f"(c.x), "f"(c.y));
    return d;
}

__device__ __forceinline__ float tanh_mufu(float x) {
    float y;
    asm("tanh.approx.f32 %0, %1;" : "=f"(y) : "f"(x));
    return y;
}

__device__ __forceinline__ float warp_sum(float v) {
    #pragma unroll
    for (int o = 16; o > 0; o >>= 1) v += __shfl_xor_sync(0xffffffffu, v, o);
    return v;
}

__device__ __forceinline__ void cp_async16(uint32_t smem_addr, const void* gptr) {
    asm volatile("cp.async.cg.shared.global [%0], [%1], 16;\n"
                 :: "r"(smem_addr), "l"(gptr));
}
__device__ __forceinline__ void cp_commit() {
    asm volatile("cp.async.commit_group;\n" ::: "memory");
}
template <int N>
__device__ __forceinline__ void cp_wait() {
    asm volatile("cp.async.wait_group %0;\n" :: "n"(N) : "memory");
}

#define RSCALE     (20.0f / 327.0f)
#define RINVSCALE  (327.0f / 20.0f)

// triangle kernel tap (antialiased bilinear downsample), unnormalized
__device__ __forceinline__ float tri(int o, float i) {
    float sf = ((float)o + 0.5f) * RINVSCALE - 0.5f;
    float x  = fabsf(sf - i) * RSCALE;
    return fmaxf(0.0f, 1.0f - x);
}

// ---------------------------------------------------------------------------
// Setup: normalized resize rows into global. grid=20 blocks x 128 thr.
// ---------------------------------------------------------------------------
__global__ __launch_bounds__(128) void phaseR_kernel() {
    __shared__ float ws[4];
    const int tid = threadIdx.x, lane = tid & 31, w = tid >> 5;
    const int o = blockIdx.x;
    float s = 0.0f;
    for (int i = tid; i < 327; i += 128) s += tri(o, (float)i);
    s = warp_sum(s);
    if (lane == 0) ws[w] = s;
    __syncthreads();
    float inv = 1.0f / (ws[0] + ws[1] + ws[2] + ws[3]);
    for (int i = tid; i < 327; i += 128)
        g_R20[o * 327 + i] = tri(o, (float)i) * inv;
}

// ---------------------------------------------------------------------------
// GroupNorm(1)+tanh for the 2-feature layout. accA = feature tid,
// accB = feature tid+128. 128 threads, 4 warps; warp w reduces samples w, w+4.
// ---------------------------------------------------------------------------
__device__ __forceinline__ void gn_tanh_store2(
    float* accA, float* accB, float* hbuf, float* mu_s, float* rs_s,
    float scA, float biA, float scB, float biB, int tid)
{
    #pragma unroll
    for (int t = 0; t < TB; t++) {
        hbuf[t * HS + tid]       = accA[t];
        hbuf[t * HS + tid + 128] = accB[t];
    }
    __syncthreads();
    int w = tid >> 5, lane = tid & 31;
    #pragma unroll
    for (int rep = 0; rep < 2; rep++) {
        int tt = w + 4 * rep;
        float s = 0.0f;
        #pragma unroll
        for (int m = 0; m < 8; m++) s += hbuf[tt * HS + lane + 32 * m];
        s = warp_sum(s);
        float mu = s * (1.0f / 256.0f);
        float q = 0.0f;
        #pragma unroll
        for (int m = 0; m < 8; m++) {
            float d = hbuf[tt * HS + lane + 32 * m] - mu;
            q = fmaf(d, d, q);
        }
        q = warp_sum(q);
        if (lane == 0) {
            mu_s[tt] = mu;
            rs_s[tt] = rsqrtf(q * (1.0f / 256.0f) + 1e-6f);
        }
    }
    __syncthreads();
    #pragma unroll
    for (int t = 0; t < TB; t++) {
        float mu = mu_s[t], rs = rs_s[t];
        hbuf[t * HS + tid]       = tanh_mufu(fmaf((accA[t] - mu) * rs, scA, biA));
        hbuf[t * HS + tid + 128] = tanh_mufu(fmaf((accB[t] - mu) * rs, scB, biB));
    }
    __syncthreads();
}

// ---------------------------------------------------------------------------
// Phase B: per distinct start s (4096 total), branch net folded through
// cW[:256] (+cb) into g_hc[s][32]. TB=8 starts/block, 128 threads,
// thread owns features (tid, tid+128). Layer-1 weights flow through a
// 4-stage cp.async smem pipeline (warp-self-contained copies).
// ---------------------------------------------------------------------------
__global__ __launch_bounds__(128, 4) void phaseB_kernel(
    const float* __restrict__ z, const float* __restrict__ zt,
    const float* __restrict__ bW0, const float* __restrict__ bb0,
    const float* __restrict__ bs0, const float* __restrict__ bB0,
    const float* __restrict__ bW1, const float* __restrict__ bb1,
    const float* __restrict__ bs1, const float* __restrict__ bB1,
    const float* __restrict__ cW,  const float* __restrict__ cb)
{
    __shared__ float e[EPAD + TB];         // sliding error window (edge-padded)
    __shared__ float obs[TB * 40];
    __shared__ float hbuf[TB * HS];        // padded stride HS (float4-aligned)
    __shared__ float wslab[4][4 * 256];    // cp.async weight pipeline (16 KB)
    __shared__ float mu_s[TB], rs_s[TB];

    const int tid = threadIdx.x;
    const int w = tid >> 5, lane = tid & 31;
    const int s0  = blockIdx.x * TB;

    // cp.async slab copy geometry (warp-self-contained):
    // warp w copies rows 0..3 x cols ([32w,32w+32) U [128+32w,128+32w+32))
    // lane = rr*8 + part; chunk = 16B = 4 floats at col 32w + 4*part.
    const int rr   = lane >> 3;            // 0..3 (k-row within slab)
    const int part = lane & 7;             // 0..7 (16B chunk within 128B)
    const int colA = 32 * w + 4 * part;    // seg 0
    const int colB = colA + 128;           // seg 1
    uint32_t slab_base = (uint32_t)__cvta_generic_to_shared(&wslab[0][0]);
    uint32_t dstA = slab_base + (rr * 256 + colA) * 4u;
    uint32_t dstB = slab_base + (rr * 256 + colB) * 4u;

    // prologue: issue 3 weight slabs (k4 = 0,1,2) before anything else
    #pragma unroll
    for (int st = 0; st < 3; st++) {
        const float* src = bW1 + (4 * st + rr) * 256;
        cp_async16(dstA + st * 4096u, src + colA);
        cp_async16(dstB + st * 4096u, src + colB);
        cp_commit();
    }

    // padded error: e[j] = error[clamp(s0 + j - HALF, 0, N_PDE-1)]
    for (int j = tid; j < EPAD + TB; j += 128) {
        int c = s0 + j - HALF;
        c = min(max(c, 0), N_PDE - 1);
        e[j] = z[c] - zt[c];
    }
    __syncthreads();

    // obs[t][o] = dot(W40[o], window(t)) — warp per row (10 rows per warp),
    // SPARSE support: <=34 taps (+margin), 2 taps per lane.
    #pragma unroll
    for (int r = 0; r < 10; r++) {
        int o = r * 4 + w;
        int p = (o < 20) ? o : o - 20;
        float sf = ((float)p + 0.5f) * RINVSCALE - 0.5f;
        int lo = (int)ceilf(sf - RINVSCALE);
        int base = max(0, lo - 1);             // -1 margin for gradient rows
        float wv[2];
        if (o < 20) {
            #pragma unroll
            for (int m = 0; m < 2; m++) {
                int i = base + lane + 32 * m;
                wv[m] = (i < 327) ? g_R20[o * 327 + i] : 0.0f;
            }
        } else {
            const float* Rp = g_R20 + p * 327;
            #pragma unroll
            for (int m = 0; m < 2; m++) {
                int i = base + lane + 32 * m;
                float v = 0.0f;
                if (i < 327) {
                    if (i >= 2)   v += 0.5f * Rp[i - 1];
                    if (i <= 324) v -= 0.5f * Rp[i + 1];
                    if (i == 0)   v -= Rp[0];
                    if (i == 1)   v += Rp[0];
                    if (i == 325) v -= Rp[326];
                    if (i == 326) v += Rp[326];
                }
                wv[m] = v;
            }
        }
        #pragma unroll
        for (int t = 0; t < TB; t++) {
            float a = fmaf(wv[0], e[t + base + lane],
                           wv[1] * e[t + base + lane + 32]);
            a = warp_sum(a);
            if (lane == 0) obs[t * 40 + o] = a;
        }
    }
    __syncthreads();

    float accA[TB], accB[TB];

    // branch layer 0: 40 -> 256, 2 features per thread, f32x2 over k-pairs
    {
        float2 aA[TB], aB[TB];
        #pragma unroll
        for (int t = 0; t < TB; t++) {
            aA[t] = make_float2(0.0f, 0.0f);
            aB[t] = make_float2(0.0f, 0.0f);
        }
        #pragma unroll 4
        for (int kk = 0; kk < 20; kk++) {
            const float* w0 = bW0 + (2 * kk) * 256;
            const float* w1 = bW0 + (2 * kk + 1) * 256;
            float2 wA = make_float2(w0[tid],       w1[tid]);
            float2 wB = make_float2(w0[tid + 128], w1[tid + 128]);
            #pragma unroll
            for (int t = 0; t < TB; t++) {
                float2 ov = *reinterpret_cast<const float2*>(&obs[t * 40 + 2 * kk]);
                aA[t] = fma2(ov, wA, aA[t]);
                aB[t] = fma2(ov, wB, aB[t]);
            }
        }
        float bA = bb0[tid], bB = bb0[tid + 128];
        #pragma unroll
        for (int t = 0; t < TB; t++) {
            accA[t] = aA[t].x + aA[t].y + bA;
            accB[t] = aB[t].x + aB[t].y + bB;
        }
    }
    gn_tanh_store2(accA, accB, hbuf, mu_s, rs_s,
                   bs0[tid], bB0[tid], bs0[tid + 128], bB0[tid + 128], tid);

    // branch layer 1: 256 -> 256. Weights arrive via the cp.async pipeline;
    // hbuf via broadcast LDS.128. No long-scoreboard stalls in steady state.
    {
        float2 aA[TB], aB[TB];
        #pragma unroll
        for (int t = 0; t < TB; t++) {
            aA[t] = make_float2(0.0f, 0.0f);
            aB[t] = make_float2(0.0f, 0.0f);
        }
        #pragma unroll 4
        for (int k4 = 0; k4 < 64; k4++) {
            const int st = k4 & 3;
            const int k = 4 * k4;
            cp_wait<2>();                    // oldest pending group (= stage st) done
            __syncwarp();
            // weights for this thread's 2 features, 4 k-rows
            const float* ws = &wslab[st][0];
            float2 wA01 = make_float2(ws[0 * 256 + tid], ws[1 * 256 + tid]);
            float2 wA23 = make_float2(ws[2 * 256 + tid], ws[3 * 256 + tid]);
            float2 wB01 = make_float2(ws[0 * 256 + tid + 128], ws[1 * 256 + tid + 128]);
            float2 wB23 = make_float2(ws[2 * 256 + tid + 128], ws[3 * 256 + tid + 128]);
            // refill stage (st+3)&3 with slab k4+3 (safe: consumed at k4-1)
            if (k4 < 61) {
                const int stn = (k4 + 3) & 3;
                const float* src = bW1 + (4 * (k4 + 3) + rr) * 256;
                cp_async16(dstA + stn * 4096u, src + colA);
                cp_async16(dstB + stn * 4096u, src + colB);
            }
            cp_commit();                     // one group per iter (may be empty)
            #pragma unroll
            for (int t = 0; t < TB; t++) {
                float4 hv = *reinterpret_cast<const float4*>(&hbuf[t * HS + k]);
                float2 hxy = make_float2(hv.x, hv.y);
                float2 hzw = make_float2(hv.z, hv.w);
                aA[t] = fma2(hxy, wA01, aA[t]);
                aA[t] = fma2(hzw, wA23, aA[t]);
                aB[t] = fma2(hxy, wB01, aB[t]);
                aB[t] = fma2(hzw, wB23, aB[t]);
            }
        }
        cp_wait<0>();                        // drain pipeline
        __syncthreads();                     // done reading h0 before gn overwrites
        float bA = bb1[tid], bB = bb1[tid + 128];
        #pragma unroll
        for (int t = 0; t < TB; t++) {
            accA[t] = aA[t].x + aA[t].y + bA;
            accB[t] = aB[t].x + aB[t].y + bB;
        }
    }
    gn_tanh_store2(accA, accB, hbuf, mu_s, rs_s,
                   bs1[tid], bB1[tid], bs1[tid + 128], bB1[tid + 128], tid);

    // fold through cW[:256] (+cb): g_hc[s][o] = h1 . cW[:,o] + cb[o]
    // 128 threads: thread handles (t, o) for t = tid>>5 and t+4.
    {
        int o = tid & 31, tb = tid >> 5;
        #pragma unroll
        for (int rep = 0; rep < 2; rep++) {
            int t = tb + 4 * rep;
            float2 a2f = make_float2(0.0f, 0.0f);
            #pragma unroll 4
            for (int k4 = 0; k4 < 64; k4++) {
                int k = 4 * k4;
                float4 hv = *reinterpret_cast<const float4*>(&hbuf[t * HS + k]);
                float c0 = cW[(k + 0) * 32 + o], c1 = cW[(k + 1) * 32 + o];
                float c2 = cW[(k + 2) * 32 + o], c3 = cW[(k + 3) * 32 + o];
                a2f = fma2(make_float2(hv.x, hv.y), make_float2(c0, c1), a2f);
                a2f = fma2(make_float2(hv.z, hv.w), make_float2(c2, c3), a2f);
            }
            g_hc[(s0 + t) * 32 + o] = a2f.x + a2f.y + cb[o];
        }
    }
}

// ---------------------------------------------------------------------------
// Phase T: tabulate final (u,v) on the xi grid: entry e = (s, k),
// xi = (s + k/3)/4095, branch part = g_hc[s]. Warp per entry, lane = neuron.
// ---------------------------------------------------------------------------
__global__ __launch_bounds__(256) void phaseT_kernel(
    const float* __restrict__ tW0, const float* __restrict__ tb0,
    const float* __restrict__ tW1, const float* __restrict__ tb1,
    const float* __restrict__ cW,
    const float* __restrict__ uW,  const float* __restrict__ ub,
    const float* __restrict__ vW,  const float* __restrict__ vb)
{
    __shared__ float sW0[8 * 32];      // [k*32+j]
    __shared__ float sW1[32 * 32];     // [k*32+j]
    __shared__ float sCt[32 * 32];     // [k*32+j] = cW[(256+k)*32+j]
    __shared__ float sb0[32], sb1[32], suW[32], svW[32];
    __shared__ float subb, svbb;

    const int tid = threadIdx.x, lane = tid & 31, wp = tid >> 5;
    if (tid < 256) {
        sW0[tid] = tW0[tid];
        if (tid < 32) {
            sb0[tid] = tb0[tid]; sb1[tid] = tb1[tid];
            suW[tid] = uW[tid];  svW[tid] = vW[tid];
        }
        if (tid == 0) { subb = ub[0]; svbb = vb[0]; }
    }
    for (int i = tid; i < 1024; i += 256) {
        sW1[i] = tW1[i];
        sCt[i] = cW[256 * 32 + i];
    }
    __syncthreads();

    int e = blockIdx.x * 8 + wp;
    if (e >= NTAB) return;
    int s = e >> 2, k = e & 3;
    float xi = ((float)s + (float)k * (1.0f / 3.0f)) * (1.0f / 4095.0f);

    const float PI = 3.14159265358979323846f;
    float p = xi * PI;
    float enc[8];
    enc[0] = __sinf(p);        enc[1] = __sinf(2.0f * p);
    enc[2] = __sinf(4.0f * p); enc[3] = __sinf(8.0f * p);
    enc[4] = __cosf(p);        enc[5] = __cosf(2.0f * p);
    enc[6] = __cosf(4.0f * p); enc[7] = __cosf(8.0f * p);

    int j = lane;
    float acc = sb0[j];
    #pragma unroll
    for (int kk = 0; kk < 8; kk++) acc = fmaf(enc[kk], sW0[kk * 32 + j], acc);
    float t0 = tanh_mufu(acc);

    acc = sb1[j];
    #pragma unroll
    for (int kk = 0; kk < 32; kk++)
        acc = fmaf(__shfl_sync(0xffffffffu, t0, kk), sW1[kk * 32 + j], acc);
    float t1 = tanh_mufu(acc);

    acc = g_hc[s * 32 + j];          // cb already folded in
    #pragma unroll
    for (int kk = 0; kk < 32; kk++)
        acc = fmaf(__shfl_sync(0xffffffffu, t1, kk), sCt[kk * 32 + j], acc);
    float xo = tanh_mufu(acc);

    float up = warp_sum(xo * suW[j]);
    float vp = warp_sum(xo * svW[j]);
    if (lane == 0)
        g_tab[e] = make_float2(40.0f * tanh_mufu(up + subb),
                               tanh_mufu(vp + svbb));
}

// ---------------------------------------------------------------------------
// Phase I: per-agent linear interpolation from the table.
// ---------------------------------------------------------------------------
__global__ __launch_bounds__(256) void phaseI_kernel(
    const float* __restrict__ xi, float* __restrict__ out, int nAgents)
{
    int a = blockIdx.x * 256 + threadIdx.x;
    if (a >= nAgents) return;
    float t = xi[a] * 4095.0f;
    int s = (int)t;                        // same truncation as reference
    float frac = t - (float)s;
    float pos = frac * 3.0f;
    int k0 = min((int)pos, 2);
    float w = pos - (float)k0;
    float2 p0 = g_tab[s * 4 + k0];
    float2 p1 = g_tab[s * 4 + k0 + 1];
    out[a]           = fmaf(w, p1.x - p0.x, p0.x);
    out[a + nAgents] = fmaf(w, p1.y - p0.y, p0.y);
}

// ---------------------------------------------------------------------------
extern "C" void kernel_launch(void* const* d_in, const int* in_sizes, int n_in,
                              void* d_out, int out_size) {
    const float* z_curr   = (const float*)d_in[0];
    const float* z_target = (const float*)d_in[1];
    const float* xi_curr  = (const float*)d_in[2];
    const float* bW0 = (const float*)d_in[3];
    const float* bb0 = (const float*)d_in[4];
    const float* bs0 = (const float*)d_in[5];
    const float* bB0 = (const float*)d_in[6];
    const float* bW1 = (const float*)d_in[7];
    const float* bb1 = (const float*)d_in[8];
    const float* bs1 = (const float*)d_in[9];
    const float* bB1 = (const float*)d_in[10];
    const float* tW0 = (const float*)d_in[11];
    const float* tb0 = (const float*)d_in[12];
    const float* tW1 = (const float*)d_in[13];
    const float* tb1 = (const float*)d_in[14];
    const float* cW  = (const float*)d_in[15];
    const float* cb  = (const float*)d_in[16];
    const float* uW  = (const float*)d_in[17];
    const float* ub  = (const float*)d_in[18];
    const float* vW  = (const float*)d_in[19];
    const float* vb  = (const float*)d_in[20];

    const int nAgents = in_sizes[2];

    phaseR_kernel<<<20, 128>>>();
    phaseB_kernel<<<NBLK_B, 128>>>(z_curr, z_target,
                                   bW0, bb0, bs0, bB0,
                                   bW1, bb1, bs1, bB1, cW, cb);
    phaseT_kernel<<<NTAB / 8, 256>>>(tW0, tb0, tW1, tb1, cW,
                                     uW, ub, vW, vb);
    phaseI_kernel<<<(nAgents + 255) / 256, 256>>>(xi_curr,
                                                  (float*)d_out, nAgents);
}

// round 14
// speedup vs baseline: 1.0039x; 1.0039x over previous
#include <cuda_runtime.h>
#include <cstdint>

#define N_PDE   4096
#define WINDOW  327
#define HALF    163
#define TB      8                  // starts per phase-B block
#define NBLK_B  (N_PDE / TB)       // 512
#define HS      260                // hbuf stride (float4-aligned, conflict-free)
#define KSUB    4                  // table samples per xi-bin
#define NTAB    (N_PDE * KSUB)     // 16384 table entries
#define EPAD    384                // padded error buffer size (covers max tap)
#define NST     8                  // cp.async pipeline stages

// Scratch (allocation-free rule: __device__ globals)
__device__ float  g_R20[20 * 327];     // normalized resize rows
__device__ float  g_hc[N_PDE * 32];    // branch output folded through cW[:256] (+cb)
__device__ float2 g_tab[NTAB];         // (u,v) final outputs on the xi grid

// ---------------------------------------------------------------------------
// helpers
// ---------------------------------------------------------------------------
__device__ __forceinline__ float2 fma2(float2 a, float2 b, float2 c) {
    float2 d;
    asm("{\n\t"
        ".reg .b64 ra, rb, rc, rd;\n\t"
        "mov.b64 ra, {%2,%3};\n\t"
        "mov.b64 rb, {%4,%5};\n\t"
        "mov.b64 rc, {%6,%7};\n\t"
        "fma.rn.f32x2 rd, ra, rb, rc;\n\t"
        "mov.b64 {%0,%1}, rd;\n\t"
        "}"
        : "=f"(d.x), "=f"(d.y)
        : "f"(a.x), "f"(a.y), "f"(b.x), "f"(b.y), "f"(c.x), "f"(c.y));
    return d;
}

__device__ __forceinline__ float tanh_mufu(float x) {
    float y;
    asm("tanh.approx.f32 %0, %1;" : "=f"(y) : "f"(x));
    return y;
}

__device__ __forceinline__ float warp_sum(float v) {
    #pragma unroll
    for (int o = 16; o > 0; o >>= 1) v += __shfl_xor_sync(0xffffffffu, v, o);
    return v;
}

__device__ __forceinline__ void cp_async16(uint32_t smem_addr, const void* gptr) {
    asm volatile("cp.async.cg.shared.global [%0], [%1], 16;\n"
                 :: "r"(smem_addr), "l"(gptr));
}
__device__ __forceinline__ void cp_commit() {
    asm volatile("cp.async.commit_group;\n" ::: "memory");
}
template <int N>
__device__ __forceinline__ void cp_wait() {
    asm volatile("cp.async.wait_group %0;\n" :: "n"(N) : "memory");
}

#define RSCALE     (20.0f / 327.0f)
#define RINVSCALE  (327.0f / 20.0f)

// triangle kernel tap (antialiased bilinear downsample), unnormalized
__device__ __forceinline__ float tri(int o, float i) {
    float sf = ((float)o + 0.5f) * RINVSCALE - 0.5f;
    float x  = fabsf(sf - i) * RSCALE;
    return fmaxf(0.0f, 1.0f - x);
}

// ---------------------------------------------------------------------------
// Setup: normalized resize rows into global. grid=20 blocks x 128 thr.
// ---------------------------------------------------------------------------
__global__ __launch_bounds__(128) void phaseR_kernel() {
    __shared__ float ws[4];
    const int tid = threadIdx.x, lane = tid & 31, w = tid >> 5;
    const int o = blockIdx.x;
    float s = 0.0f;
    for (int i = tid; i < 327; i += 128) s += tri(o, (float)i);
    s = warp_sum(s);
    if (lane == 0) ws[w] = s;
    __syncthreads();
    float inv = 1.0f / (ws[0] + ws[1] + ws[2] + ws[3]);
    for (int i = tid; i < 327; i += 128)
        g_R20[o * 327 + i] = tri(o, (float)i) * inv;
}

// ---------------------------------------------------------------------------
// GroupNorm(1)+tanh for the 2-feature layout. accA = feature tid,
// accB = feature tid+128. 128 threads, 4 warps; warp w reduces samples w, w+4.
// ---------------------------------------------------------------------------
__device__ __forceinline__ void gn_tanh_store2(
    float* accA, float* accB, float* hbuf, float* mu_s, float* rs_s,
    float scA, float biA, float scB, float biB, int tid)
{
    #pragma unroll
    for (int t = 0; t < TB; t++) {
        hbuf[t * HS + tid]       = accA[t];
        hbuf[t * HS + tid + 128] = accB[t];
    }
    __syncthreads();
    int w = tid >> 5, lane = tid & 31;
    #pragma unroll
    for (int rep = 0; rep < 2; rep++) {
        int tt = w + 4 * rep;
        float s = 0.0f;
        #pragma unroll
        for (int m = 0; m < 8; m++) s += hbuf[tt * HS + lane + 32 * m];
        s = warp_sum(s);
        float mu = s * (1.0f / 256.0f);
        float q = 0.0f;
        #pragma unroll
        for (int m = 0; m < 8; m++) {
            float d = hbuf[tt * HS + lane + 32 * m] - mu;
            q = fmaf(d, d, q);
        }
        q = warp_sum(q);
        if (lane == 0) {
            mu_s[tt] = mu;
            rs_s[tt] = rsqrtf(q * (1.0f / 256.0f) + 1e-6f);
        }
    }
    __syncthreads();
    #pragma unroll
    for (int t = 0; t < TB; t++) {
        float mu = mu_s[t], rs = rs_s[t];
        hbuf[t * HS + tid]       = tanh_mufu(fmaf((accA[t] - mu) * rs, scA, biA));
        hbuf[t * HS + tid + 128] = tanh_mufu(fmaf((accB[t] - mu) * rs, scB, biB));
    }
    __syncthreads();
}

// ---------------------------------------------------------------------------
// Phase B: per distinct start s (4096 total), branch net folded through
// cW[:256] (+cb) into g_hc[s][32]. TB=8 starts/block, 128 threads,
// thread owns features (tid, tid+128). Layer-1 weights flow through an
// 8-stage cp.async smem pipeline (warp-self-contained copies); pipeline
// depth (7 slabs of lead) exceeds the L2-hit latency.
// ---------------------------------------------------------------------------
__global__ __launch_bounds__(128, 4) void phaseB_kernel(
    const float* __restrict__ z, const float* __restrict__ zt,
    const float* __restrict__ bW0, const float* __restrict__ bb0,
    const float* __restrict__ bs0, const float* __restrict__ bB0,
    const float* __restrict__ bW1, const float* __restrict__ bb1,
    const float* __restrict__ bs1, const float* __restrict__ bB1,
    const float* __restrict__ cW,  const float* __restrict__ cb)
{
    __shared__ float e[EPAD + TB];         // sliding error window (edge-padded)
    __shared__ float obs[TB * 40];
    __shared__ float hbuf[TB * HS];        // padded stride HS (float4-aligned)
    __shared__ float wslab[NST][4 * 256];  // cp.async weight pipeline (32 KB)
    __shared__ float mu_s[TB], rs_s[TB];

    const int tid = threadIdx.x;
    const int w = tid >> 5, lane = tid & 31;
    const int s0  = blockIdx.x * TB;

    // cp.async slab copy geometry (warp-self-contained):
    // warp w copies rows 0..3 x cols ([32w,32w+32) U [128+32w,128+32w+32))
    // lane = rr*8 + part; chunk = 16B = 4 floats at col 32w + 4*part.
    const int rr   = lane >> 3;            // 0..3 (k-row within slab)
    const int part = lane & 7;             // 0..7 (16B chunk within 128B)
    const int colA = 32 * w + 4 * part;    // seg 0
    const int colB = colA + 128;           // seg 1
    uint32_t slab_base = (uint32_t)__cvta_generic_to_shared(&wslab[0][0]);
    uint32_t dstA = slab_base + (rr * 256 + colA) * 4u;
    uint32_t dstB = slab_base + (rr * 256 + colB) * 4u;

    // prologue: issue NST-1 = 7 weight slabs (k4 = 0..6) before anything else
    #pragma unroll
    for (int st = 0; st < NST - 1; st++) {
        const float* src = bW1 + (4 * st + rr) * 256;
        cp_async16(dstA + st * 4096u, src + colA);
        cp_async16(dstB + st * 4096u, src + colB);
        cp_commit();
    }

    // padded error: e[j] = error[clamp(s0 + j - HALF, 0, N_PDE-1)]
    for (int j = tid; j < EPAD + TB; j += 128) {
        int c = s0 + j - HALF;
        c = min(max(c, 0), N_PDE - 1);
        e[j] = z[c] - zt[c];
    }
    __syncthreads();

    // obs[t][o] = dot(W40[o], window(t)) — warp per row (10 rows per warp),
    // SPARSE support: <=34 taps (+margin), 2 taps per lane.
    #pragma unroll
    for (int r = 0; r < 10; r++) {
        int o = r * 4 + w;
        int p = (o < 20) ? o : o - 20;
        float sf = ((float)p + 0.5f) * RINVSCALE - 0.5f;
        int lo = (int)ceilf(sf - RINVSCALE);
        int base = max(0, lo - 1);             // -1 margin for gradient rows
        float wv[2];
        if (o < 20) {
            #pragma unroll
            for (int m = 0; m < 2; m++) {
                int i = base + lane + 32 * m;
                wv[m] = (i < 327) ? g_R20[o * 327 + i] : 0.0f;
            }
        } else {
            const float* Rp = g_R20 + p * 327;
            #pragma unroll
            for (int m = 0; m < 2; m++) {
                int i = base + lane + 32 * m;
                float v = 0.0f;
                if (i < 327) {
                    if (i >= 2)   v += 0.5f * Rp[i - 1];
                    if (i <= 324) v -= 0.5f * Rp[i + 1];
                    if (i == 0)   v -= Rp[0];
                    if (i == 1)   v += Rp[0];
                    if (i == 325) v -= Rp[326];
                    if (i == 326) v += Rp[326];
                }
                wv[m] = v;
            }
        }
        #pragma unroll
        for (int t = 0; t < TB; t++) {
            float a = fmaf(wv[0], e[t + base + lane],
                           wv[1] * e[t + base + lane + 32]);
            a = warp_sum(a);
            if (lane == 0) obs[t * 40 + o] = a;
        }
    }
    __syncthreads();

    float accA[TB], accB[TB];

    // branch layer 0: 40 -> 256, 2 features per thread, f32x2 over k-pairs
    {
        float2 aA[TB], aB[TB];
        #pragma unroll
        for (int t = 0; t < TB; t++) {
            aA[t] = make_float2(0.0f, 0.0f);
            aB[t] = make_float2(0.0f, 0.0f);
        }
        #pragma unroll 4
        for (int kk = 0; kk < 20; kk++) {
            const float* w0 = bW0 + (2 * kk) * 256;
            const float* w1 = bW0 + (2 * kk + 1) * 256;
            float2 wA = make_float2(w0[tid],       w1[tid]);
            float2 wB = make_float2(w0[tid + 128], w1[tid + 128]);
            #pragma unroll
            for (int t = 0; t < TB; t++) {
                float2 ov = *reinterpret_cast<const float2*>(&obs[t * 40 + 2 * kk]);
                aA[t] = fma2(ov, wA, aA[t]);
                aB[t] = fma2(ov, wB, aB[t]);
            }
        }
        float bA = bb0[tid], bB = bb0[tid + 128];
        #pragma unroll
        for (int t = 0; t < TB; t++) {
            accA[t] = aA[t].x + aA[t].y + bA;
            accB[t] = aB[t].x + aB[t].y + bB;
        }
    }
    gn_tanh_store2(accA, accB, hbuf, mu_s, rs_s,
                   bs0[tid], bB0[tid], bs0[tid + 128], bB0[tid + 128], tid);

    // branch layer 1: 256 -> 256. Weights arrive via the deep cp.async
    // pipeline; hbuf via broadcast LDS.128.
    {
        float2 aA[TB], aB[TB];
        #pragma unroll
        for (int t = 0; t < TB; t++) {
            aA[t] = make_float2(0.0f, 0.0f);
            aB[t] = make_float2(0.0f, 0.0f);
        }
        #pragma unroll 4
        for (int k4 = 0; k4 < 64; k4++) {
            const int st = k4 & (NST - 1);
            const int k = 4 * k4;
            cp_wait<NST - 2>();              // slab k4 resident (<=6 pending)
            __syncwarp();
            // weights for this thread's 2 features, 4 k-rows
            const float* ws = &wslab[st][0];
            float2 wA01 = make_float2(ws[0 * 256 + tid], ws[1 * 256 + tid]);
            float2 wA23 = make_float2(ws[2 * 256 + tid], ws[3 * 256 + tid]);
            float2 wB01 = make_float2(ws[0 * 256 + tid + 128], ws[1 * 256 + tid + 128]);
            float2 wB23 = make_float2(ws[2 * 256 + tid + 128], ws[3 * 256 + tid + 128]);
            // refill stage (st+NST-1)&(NST-1) with slab k4+NST-1
            if (k4 < 64 - (NST - 1)) {
                const int stn = (k4 + NST - 1) & (NST - 1);
                const float* src = bW1 + (4 * (k4 + NST - 1) + rr) * 256;
                cp_async16(dstA + stn * 4096u, src + colA);
                cp_async16(dstB + stn * 4096u, src + colB);
            }
            cp_commit();                     // one group per iter (may be empty)
            #pragma unroll
            for (int t = 0; t < TB; t++) {
                float4 hv = *reinterpret_cast<const float4*>(&hbuf[t * HS + k]);
                float2 hxy = make_float2(hv.x, hv.y);
                float2 hzw = make_float2(hv.z, hv.w);
                aA[t] = fma2(hxy, wA01, aA[t]);
                aA[t] = fma2(hzw, wA23, aA[t]);
                aB[t] = fma2(hxy, wB01, aB[t]);
                aB[t] = fma2(hzw, wB23, aB[t]);
            }
        }
        cp_wait<0>();                        // drain pipeline
        __syncthreads();                     // done reading h0 before gn overwrites
        float bA = bb1[tid], bB = bb1[tid + 128];
        #pragma unroll
        for (int t = 0; t < TB; t++) {
            accA[t] = aA[t].x + aA[t].y + bA;
            accB[t] = aB[t].x + aB[t].y + bB;
        }
    }
    gn_tanh_store2(accA, accB, hbuf, mu_s, rs_s,
                   bs1[tid], bB1[tid], bs1[tid + 128], bB1[tid + 128], tid);

    // fold through cW[:256] (+cb): g_hc[s][o] = h1 . cW[:,o] + cb[o]
    // 128 threads: thread handles (t, o) for t = tid>>5 and t+4.
    {
        int o = tid & 31, tb = tid >> 5;
        #pragma unroll
        for (int rep = 0; rep < 2; rep++) {
            int t = tb + 4 * rep;
            float2 a2f = make_float2(0.0f, 0.0f);
            #pragma unroll 4
            for (int k4 = 0; k4 < 64; k4++) {
                int k = 4 * k4;
                float4 hv = *reinterpret_cast<const float4*>(&hbuf[t * HS + k]);
                float c0 = cW[(k + 0) * 32 + o], c1 = cW[(k + 1) * 32 + o];
                float c2 = cW[(k + 2) * 32 + o], c3 = cW[(k + 3) * 32 + o];
                a2f = fma2(make_float2(hv.x, hv.y), make_float2(c0, c1), a2f);
                a2f = fma2(make_float2(hv.z, hv.w), make_float2(c2, c3), a2f);
            }
            g_hc[(s0 + t) * 32 + o] = a2f.x + a2f.y + cb[o];
        }
    }
}

// ---------------------------------------------------------------------------
// Phase T: tabulate final (u,v) on the xi grid: entry e = (s, k),
// xi = (s + k/3)/4095, branch part = g_hc[s]. Warp per entry, lane = neuron.
// ---------------------------------------------------------------------------
__global__ __launch_bounds__(256) void phaseT_kernel(
    const float* __restrict__ tW0, const float* __restrict__ tb0,
    const float* __restrict__ tW1, const float* __restrict__ tb1,
    const float* __restrict__ cW,
    const float* __restrict__ uW,  const float* __restrict__ ub,
    const float* __restrict__ vW,  const float* __restrict__ vb)
{
    __shared__ float sW0[8 * 32];      // [k*32+j]
    __shared__ float sW1[32 * 32];     // [k*32+j]
    __shared__ float sCt[32 * 32];     // [k*32+j] = cW[(256+k)*32+j]
    __shared__ float sb0[32], sb1[32], suW[32], svW[32];
    __shared__ float subb, svbb;

    const int tid = threadIdx.x, lane = tid & 31, wp = tid >> 5;
    if (tid < 256) {
        sW0[tid] = tW0[tid];
        if (tid < 32) {
            sb0[tid] = tb0[tid]; sb1[tid] = tb1[tid];
            suW[tid] = uW[tid];  svW[tid] = vW[tid];
        }
        if (tid == 0) { subb = ub[0]; svbb = vb[0]; }
    }
    for (int i = tid; i < 1024; i += 256) {
        sW1[i] = tW1[i];
        sCt[i] = cW[256 * 32 + i];
    }
    __syncthreads();

    int e = blockIdx.x * 8 + wp;
    if (e >= NTAB) return;
    int s = e >> 2, k = e & 3;
    float xi = ((float)s + (float)k * (1.0f / 3.0f)) * (1.0f / 4095.0f);

    const float PI = 3.14159265358979323846f;
    float p = xi * PI;
    float enc[8];
    enc[0] = __sinf(p);        enc[1] = __sinf(2.0f * p);
    enc[2] = __sinf(4.0f * p); enc[3] = __sinf(8.0f * p);
    enc[4] = __cosf(p);        enc[5] = __cosf(2.0f * p);
    enc[6] = __cosf(4.0f * p); enc[7] = __cosf(8.0f * p);

    int j = lane;
    float acc = sb0[j];
    #pragma unroll
    for (int kk = 0; kk < 8; kk++) acc = fmaf(enc[kk], sW0[kk * 32 + j], acc);
    float t0 = tanh_mufu(acc);

    acc = sb1[j];
    #pragma unroll
    for (int kk = 0; kk < 32; kk++)
        acc = fmaf(__shfl_sync(0xffffffffu, t0, kk), sW1[kk * 32 + j], acc);
    float t1 = tanh_mufu(acc);

    acc = g_hc[s * 32 + j];          // cb already folded in
    #pragma unroll
    for (int kk = 0; kk < 32; kk++)
        acc = fmaf(__shfl_sync(0xffffffffu, t1, kk), sCt[kk * 32 + j], acc);
    float xo = tanh_mufu(acc);

    float up = warp_sum(xo * suW[j]);
    float vp = warp_sum(xo * svW[j]);
    if (lane == 0)
        g_tab[e] = make_float2(40.0f * tanh_mufu(up + subb),
                               tanh_mufu(vp + svbb));
}

// ---------------------------------------------------------------------------
// Phase I: per-agent linear interpolation, 4 agents per thread for MLP.
// ---------------------------------------------------------------------------
__global__ __launch_bounds__(256) void phaseI_kernel(
    const float* __restrict__ xi, float* __restrict__ out, int nAgents)
{
    int base = blockIdx.x * 1024 + threadIdx.x;

    int   a[4];  bool v[4];  float tt[4];
    #pragma unroll
    for (int r = 0; r < 4; r++) {
        a[r] = base + 256 * r;
        v[r] = a[r] < nAgents;
        tt[r] = v[r] ? xi[a[r]] : 0.0f;
    }

    float2 p0[4], p1[4]; float wq[4];
    #pragma unroll
    for (int r = 0; r < 4; r++) {
        float t = tt[r] * 4095.0f;
        int s = (int)t;                    // same truncation as reference
        float pos = (t - (float)s) * 3.0f;
        int k0 = min((int)pos, 2);
        wq[r] = pos - (float)k0;
        int idx = s * 4 + k0;
        p0[r] = g_tab[idx];
        p1[r] = g_tab[idx + 1];
    }

    #pragma unroll
    for (int r = 0; r < 4; r++) {
        if (v[r]) {
            out[a[r]]           = fmaf(wq[r], p1[r].x - p0[r].x, p0[r].x);
            out[a[r] + nAgents] = fmaf(wq[r], p1[r].y - p0[r].y, p0[r].y);
        }
    }
}

// ---------------------------------------------------------------------------
extern "C" void kernel_launch(void* const* d_in, const int* in_sizes, int n_in,
                              void* d_out, int out_size) {
    const float* z_curr   = (const float*)d_in[0];
    const float* z_target = (const float*)d_in[1];
    const float* xi_curr  = (const float*)d_in[2];
    const float* bW0 = (const float*)d_in[3];
    const float* bb0 = (const float*)d_in[4];
    const float* bs0 = (const float*)d_in[5];
    const float* bB0 = (const float*)d_in[6];
    const float* bW1 = (const float*)d_in[7];
    const float* bb1 = (const float*)d_in[8];
    const float* bs1 = (const float*)d_in[9];
    const float* bB1 = (const float*)d_in[10];
    const float* tW0 = (const float*)d_in[11];
    const float* tb0 = (const float*)d_in[12];
    const float* tW1 = (const float*)d_in[13];
    const float* tb1 = (const float*)d_in[14];
    const float* cW  = (const float*)d_in[15];
    const float* cb  = (const float*)d_in[16];
    const float* uW  = (const float*)d_in[17];
    const float* ub  = (const float*)d_in[18];
    const float* vW  = (const float*)d_in[19];
    const float* vb  = (const float*)d_in[20];

    const int nAgents = in_sizes[2];

    phaseR_kernel<<<20, 128>>>();
    phaseB_kernel<<<NBLK_B, 128>>>(z_curr, z_target,
                                   bW0, bb0, bs0, bB0,
                                   bW1, bb1, bs1, bB1, cW, cb);
    phaseT_kernel<<<NTAB / 8, 256>>>(tW0, tb0, tW1, tb1, cW,
                                     uW, ub, vW, vb);
    phaseI_kernel<<<(nAgents + 1023) / 1024, 256>>>(xi_curr,
                                                    (float*)d_out, nAgents);
}

// round 15
// speedup vs baseline: 1.0804x; 1.0762x over previous
#include <cuda_runtime.h>
#include <cstdint>

#define N_PDE   4096
#define WINDOW  327
#define HALF    163
#define TB      8                  // starts per phase-B block
#define NBLK_B  (N_PDE / TB)       // 512
#define HS      260                // hbuf stride (float4-aligned, conflict-free)
#define KSUB    4                  // table samples per xi-bin
#define NTAB    (N_PDE * KSUB)     // 16384 table entries
#define EPAD    384                // padded error buffer size
#define ESZ     (EPAD + TB)        // e[] / ecd[] length

// Scratch (allocation-free rule: __device__ globals)
__device__ float  g_R20[20 * 327];     // normalized resize rows
__device__ float  g_hc[N_PDE * 32];    // branch output folded through cW[:256] (+cb)
__device__ float2 g_tab[NTAB];         // (u,v) final outputs on the xi grid

// ---------------------------------------------------------------------------
// helpers
// ---------------------------------------------------------------------------
__device__ __forceinline__ float2 fma2(float2 a, float2 b, float2 c) {
    float2 d;
    asm("{\n\t"
        ".reg .b64 ra, rb, rc, rd;\n\t"
        "mov.b64 ra, {%2,%3};\n\t"
        "mov.b64 rb, {%4,%5};\n\t"
        "mov.b64 rc, {%6,%7};\n\t"
        "fma.rn.f32x2 rd, ra, rb, rc;\n\t"
        "mov.b64 {%0,%1}, rd;\n\t"
        "}"
        : "=f"(d.x), "=f"(d.y)
        : "f"(a.x), "f"(a.y), "f"(b.x), "f"(b.y), "f"(c.x), "f"(c.y));
    return d;
}

__device__ __forceinline__ float tanh_mufu(float x) {
    float y;
    asm("tanh.approx.f32 %0, %1;" : "=f"(y) : "f"(x));
    return y;
}

__device__ __forceinline__ float warp_sum(float v) {
    #pragma unroll
    for (int o = 16; o > 0; o >>= 1) v += __shfl_xor_sync(0xffffffffu, v, o);
    return v;
}

#define RSCALE     (20.0f / 327.0f)
#define RINVSCALE  (327.0f / 20.0f)

// triangle kernel tap (antialiased bilinear downsample), unnormalized
__device__ __forceinline__ float tri(int o, float i) {
    float sf = ((float)o + 0.5f) * RINVSCALE - 0.5f;
    float x  = fabsf(sf - i) * RSCALE;
    return fmaxf(0.0f, 1.0f - x);
}

// ---------------------------------------------------------------------------
// Setup: normalized resize rows into global. grid=20 blocks x 128 thr.
// ---------------------------------------------------------------------------
__global__ __launch_bounds__(128) void phaseR_kernel() {
    __shared__ float ws[4];
    const int tid = threadIdx.x, lane = tid & 31, w = tid >> 5;
    const int o = blockIdx.x;
    float s = 0.0f;
    for (int i = tid; i < 327; i += 128) s += tri(o, (float)i);
    s = warp_sum(s);
    if (lane == 0) ws[w] = s;
    __syncthreads();
    float inv = 1.0f / (ws[0] + ws[1] + ws[2] + ws[3]);
    for (int i = tid; i < 327; i += 128)
        g_R20[o * 327 + i] = tri(o, (float)i) * inv;
}

// ---------------------------------------------------------------------------
// GroupNorm(1)+tanh for the 2-feature layout. accA = feature tid,
// accB = feature tid+128. 128 threads, 4 warps; warp w reduces samples w, w+4.
// ---------------------------------------------------------------------------
__device__ __forceinline__ void gn_tanh_store2(
    float* accA, float* accB, float* hbuf, float* mu_s, float* rs_s,
    float scA, float biA, float scB, float biB, int tid)
{
    #pragma unroll
    for (int t = 0; t < TB; t++) {
        hbuf[t * HS + tid]       = accA[t];
        hbuf[t * HS + tid + 128] = accB[t];
    }
    __syncthreads();
    int w = tid >> 5, lane = tid & 31;
    #pragma unroll
    for (int rep = 0; rep < 2; rep++) {
        int tt = w + 4 * rep;
        float s = 0.0f;
        #pragma unroll
        for (int m = 0; m < 8; m++) s += hbuf[tt * HS + lane + 32 * m];
        s = warp_sum(s);
        float mu = s * (1.0f / 256.0f);
        float q = 0.0f;
        #pragma unroll
        for (int m = 0; m < 8; m++) {
            float d = hbuf[tt * HS + lane + 32 * m] - mu;
            q = fmaf(d, d, q);
        }
        q = warp_sum(q);
        if (lane == 0) {
            mu_s[tt] = mu;
            rs_s[tt] = rsqrtf(q * (1.0f / 256.0f) + 1e-6f);
        }
    }
    __syncthreads();
    #pragma unroll
    for (int t = 0; t < TB; t++) {
        float mu = mu_s[t], rs = rs_s[t];
        hbuf[t * HS + tid]       = tanh_mufu(fmaf((accA[t] - mu) * rs, scA, biA));
        hbuf[t * HS + tid + 128] = tanh_mufu(fmaf((accB[t] - mu) * rs, scB, biB));
    }
    __syncthreads();
}

// ---------------------------------------------------------------------------
// Phase B: per distinct start s (4096 total), branch net folded through
// cW[:256] (+cb) into g_hc[s][32]. TB=8 starts/block, 128 threads,
// thread owns features (tid, tid+128). obs stage is thread-parallel:
// gradient rows reuse resize-row weights on a central-diff array ecd[].
// ---------------------------------------------------------------------------
__global__ __launch_bounds__(128, 4) void phaseB_kernel(
    const float* __restrict__ z, const float* __restrict__ zt,
    const float* __restrict__ bW0, const float* __restrict__ bb0,
    const float* __restrict__ bs0, const float* __restrict__ bB0,
    const float* __restrict__ bW1, const float* __restrict__ bb1,
    const float* __restrict__ bs1, const float* __restrict__ bB1,
    const float* __restrict__ cW,  const float* __restrict__ cb)
{
    __shared__ float e[ESZ];               // sliding error window (edge-padded)
    __shared__ float ecd[ESZ];             // central diff of e (shared over t)
    __shared__ float obs[TB * 40];
    __shared__ float hbuf[TB * HS];        // padded stride HS (float4-aligned)
    __shared__ float mu_s[TB], rs_s[TB];

    const int tid = threadIdx.x;
    const int s0  = blockIdx.x * TB;

    // padded error: e[j] = error[clamp(s0 + j - HALF, 0, N_PDE-1)]
    for (int j = tid; j < ESZ; j += 128) {
        int c = s0 + j - HALF;
        c = min(max(c, 0), N_PDE - 1);
        e[j] = z[c] - zt[c];
    }
    __syncthreads();

    // central diff (clamped ends; end values cancel in the fixups)
    for (int j = tid; j < ESZ; j += 128) {
        int jm = max(j - 1, 0), jp = min(j + 1, ESZ - 1);
        ecd[j] = 0.5f * (e[jp] - e[jm]);
    }
    __syncthreads();

    // obs: 160 (t,p) pairs over 128 threads; each produces obs[t][p] (resize)
    // and obs[t][20+p] (gradient) with the SAME 34-tap weight row.
    for (int pi = tid; pi < TB * 20; pi += 128) {
        int t = pi / 20, p = pi - 20 * (pi / 20);
        float sf = ((float)p + 0.5f) * RINVSCALE - 0.5f;
        int base = max(0, (int)ceilf(sf - RINVSCALE));
        const float* Rp = g_R20 + p * 327;
        float accR = 0.0f, accG = 0.0f;
        #pragma unroll 2
        for (int m = 0; m < 34; m++) {
            int i = base + m;
            float wv = (i < 327) ? Rp[i] : 0.0f;
            accR = fmaf(wv, e[t + i],   accR);
            accG = fmaf(wv, ecd[t + i], accG);
        }
        if (p == 0) {                      // one-sided diff at window start
            float R0 = Rp[0];
            accG += R0 * ((e[t + 1] - e[t]) - ecd[t]);
        }
        if (p == 19) {                     // one-sided diff at window end
            float R326 = Rp[326];
            accG += R326 * ((e[t + 326] - e[t + 325]) - ecd[t + 326]);
        }
        obs[t * 40 + p]      = accR;
        obs[t * 40 + 20 + p] = accG;
    }
    __syncthreads();

    float accA[TB], accB[TB];

    // branch layer 0: 40 -> 256, 2 features per thread, f32x2 over k-pairs
    {
        float2 aA[TB], aB[TB];
        #pragma unroll
        for (int t = 0; t < TB; t++) {
            aA[t] = make_float2(0.0f, 0.0f);
            aB[t] = make_float2(0.0f, 0.0f);
        }
        #pragma unroll 4
        for (int kk = 0; kk < 20; kk++) {
            const float* w0 = bW0 + (2 * kk) * 256;
            const float* w1 = bW0 + (2 * kk + 1) * 256;
            float2 wA = make_float2(w0[tid],       w1[tid]);
            float2 wB = make_float2(w0[tid + 128], w1[tid + 128]);
            #pragma unroll
            for (int t = 0; t < TB; t++) {
                float2 ov = *reinterpret_cast<const float2*>(&obs[t * 40 + 2 * kk]);
                aA[t] = fma2(ov, wA, aA[t]);
                aB[t] = fma2(ov, wB, aB[t]);
            }
        }
        float bA = bb0[tid], bB = bb0[tid + 128];
        #pragma unroll
        for (int t = 0; t < TB; t++) {
            accA[t] = aA[t].x + aA[t].y + bA;
            accB[t] = aB[t].x + aB[t].y + bB;
        }
    }
    gn_tanh_store2(accA, accB, hbuf, mu_s, rs_s,
                   bs0[tid], bB0[tid], bs0[tid + 128], bB0[tid + 128], tid);

    // branch layer 1: 256 -> 256, float4 LDS shared by both features
    {
        float2 aA[TB], aB[TB];
        #pragma unroll
        for (int t = 0; t < TB; t++) {
            aA[t] = make_float2(0.0f, 0.0f);
            aB[t] = make_float2(0.0f, 0.0f);
        }
        #pragma unroll 2
        for (int k4 = 0; k4 < 64; k4++) {
            int k = 4 * k4;
            const float* r0 = bW1 + (k + 0) * 256;
            const float* r1 = bW1 + (k + 1) * 256;
            const float* r2 = bW1 + (k + 2) * 256;
            const float* r3 = bW1 + (k + 3) * 256;
            float2 wA01 = make_float2(r0[tid], r1[tid]);
            float2 wA23 = make_float2(r2[tid], r3[tid]);
            float2 wB01 = make_float2(r0[tid + 128], r1[tid + 128]);
            float2 wB23 = make_float2(r2[tid + 128], r3[tid + 128]);
            #pragma unroll
            for (int t = 0; t < TB; t++) {
                float4 hv = *reinterpret_cast<const float4*>(&hbuf[t * HS + k]);
                float2 hxy = make_float2(hv.x, hv.y);
                float2 hzw = make_float2(hv.z, hv.w);
                aA[t] = fma2(hxy, wA01, aA[t]);
                aA[t] = fma2(hzw, wA23, aA[t]);
                aB[t] = fma2(hxy, wB01, aB[t]);
                aB[t] = fma2(hzw, wB23, aB[t]);
            }
        }
        __syncthreads();                   // done reading h0 before gn overwrites
        float bA = bb1[tid], bB = bb1[tid + 128];
        #pragma unroll
        for (int t = 0; t < TB; t++) {
            accA[t] = aA[t].x + aA[t].y + bA;
            accB[t] = aB[t].x + aB[t].y + bB;
        }
    }
    gn_tanh_store2(accA, accB, hbuf, mu_s, rs_s,
                   bs1[tid], bB1[tid], bs1[tid + 128], bB1[tid + 128], tid);

    // fold through cW[:256] (+cb): g_hc[s][o] = h1 . cW[:,o] + cb[o]
    // 128 threads: thread handles (t, o) for t = tid>>5 and t+4.
    {
        int o = tid & 31, tb = tid >> 5;
        #pragma unroll
        for (int rep = 0; rep < 2; rep++) {
            int t = tb + 4 * rep;
            float2 a2f = make_float2(0.0f, 0.0f);
            #pragma unroll 4
            for (int k4 = 0; k4 < 64; k4++) {
                int k = 4 * k4;
                float4 hv = *reinterpret_cast<const float4*>(&hbuf[t * HS + k]);
                float c0 = cW[(k + 0) * 32 + o], c1 = cW[(k + 1) * 32 + o];
                float c2 = cW[(k + 2) * 32 + o], c3 = cW[(k + 3) * 32 + o];
                a2f = fma2(make_float2(hv.x, hv.y), make_float2(c0, c1), a2f);
                a2f = fma2(make_float2(hv.z, hv.w), make_float2(c2, c3), a2f);
            }
            g_hc[(s0 + t) * 32 + o] = a2f.x + a2f.y + cb[o];
        }
    }
}

// ---------------------------------------------------------------------------
// Phase T: tabulate final (u,v) on the xi grid: entry e = (s, k),
// xi = (s + k/3)/4095, branch part = g_hc[s]. Warp per entry, lane = neuron.
// ---------------------------------------------------------------------------
__global__ __launch_bounds__(256) void phaseT_kernel(
    const float* __restrict__ tW0, const float* __restrict__ tb0,
    const float* __restrict__ tW1, const float* __restrict__ tb1,
    const float* __restrict__ cW,
    const float* __restrict__ uW,  const float* __restrict__ ub,
    const float* __restrict__ vW,  const float* __restrict__ vb)
{
    __shared__ float sW0[8 * 32];      // [k*32+j]
    __shared__ float sW1[32 * 32];     // [k*32+j]
    __shared__ float sCt[32 * 32];     // [k*32+j] = cW[(256+k)*32+j]
    __shared__ float sb0[32], sb1[32], suW[32], svW[32];
    __shared__ float subb, svbb;

    const int tid = threadIdx.x, lane = tid & 31, wp = tid >> 5;
    if (tid < 256) {
        sW0[tid] = tW0[tid];
        if (tid < 32) {
            sb0[tid] = tb0[tid]; sb1[tid] = tb1[tid];
            suW[tid] = uW[tid];  svW[tid] = vW[tid];
        }
        if (tid == 0) { subb = ub[0]; svbb = vb[0]; }
    }
    for (int i = tid; i < 1024; i += 256) {
        sW1[i] = tW1[i];
        sCt[i] = cW[256 * 32 + i];
    }
    __syncthreads();

    int e = blockIdx.x * 8 + wp;
    if (e >= NTAB) return;
    int s = e >> 2, k = e & 3;
    float xi = ((float)s + (float)k * (1.0f / 3.0f)) * (1.0f / 4095.0f);

    const float PI = 3.14159265358979323846f;
    float p = xi * PI;
    float enc[8];
    enc[0] = __sinf(p);        enc[1] = __sinf(2.0f * p);
    enc[2] = __sinf(4.0f * p); enc[3] = __sinf(8.0f * p);
    enc[4] = __cosf(p);        enc[5] = __cosf(2.0f * p);
    enc[6] = __cosf(4.0f * p); enc[7] = __cosf(8.0f * p);

    int j = lane;
    float acc = sb0[j];
    #pragma unroll
    for (int kk = 0; kk < 8; kk++) acc = fmaf(enc[kk], sW0[kk * 32 + j], acc);
    float t0 = tanh_mufu(acc);

    acc = sb1[j];
    #pragma unroll
    for (int kk = 0; kk < 32; kk++)
        acc = fmaf(__shfl_sync(0xffffffffu, t0, kk), sW1[kk * 32 + j], acc);
    float t1 = tanh_mufu(acc);

    acc = g_hc[s * 32 + j];          // cb already folded in
    #pragma unroll
    for (int kk = 0; kk < 32; kk++)
        acc = fmaf(__shfl_sync(0xffffffffu, t1, kk), sCt[kk * 32 + j], acc);
    float xo = tanh_mufu(acc);

    float up = warp_sum(xo * suW[j]);
    float vp = warp_sum(xo * svW[j]);
    if (lane == 0)
        g_tab[e] = make_float2(40.0f * tanh_mufu(up + subb),
                               tanh_mufu(vp + svbb));
}

// ---------------------------------------------------------------------------
// Phase I: per-agent linear interpolation from the table.
// ---------------------------------------------------------------------------
__global__ __launch_bounds__(256) void phaseI_kernel(
    const float* __restrict__ xi, float* __restrict__ out, int nAgents)
{
    int a = blockIdx.x * 256 + threadIdx.x;
    if (a >= nAgents) return;
    float t = xi[a] * 4095.0f;
    int s = (int)t;                        // same truncation as reference
    float frac = t - (float)s;
    float pos = frac * 3.0f;
    int k0 = min((int)pos, 2);
    float w = pos - (float)k0;
    float2 p0 = g_tab[s * 4 + k0];
    float2 p1 = g_tab[s * 4 + k0 + 1];
    out[a]           = fmaf(w, p1.x - p0.x, p0.x);
    out[a + nAgents] = fmaf(w, p1.y - p0.y, p0.y);
}

// ---------------------------------------------------------------------------
extern "C" void kernel_launch(void* const* d_in, const int* in_sizes, int n_in,
                              void* d_out, int out_size) {
    const float* z_curr   = (const float*)d_in[0];
    const float* z_target = (const float*)d_in[1];
    const float* xi_curr  = (const float*)d_in[2];
    const float* bW0 = (const float*)d_in[3];
    const float* bb0 = (const float*)d_in[4];
    const float* bs0 = (const float*)d_in[5];
    const float* bB0 = (const float*)d_in[6];
    const float* bW1 = (const float*)d_in[7];
    const float* bb1 = (const float*)d_in[8];
    const float* bs1 = (const float*)d_in[9];
    const float* bB1 = (const float*)d_in[10];
    const float* tW0 = (const float*)d_in[11];
    const float* tb0 = (const float*)d_in[12];
    const float* tW1 = (const float*)d_in[13];
    const float* tb1 = (const float*)d_in[14];
    const float* cW  = (const float*)d_in[15];
    const float* cb  = (const float*)d_in[16];
    const float* uW  = (const float*)d_in[17];
    const float* ub  = (const float*)d_in[18];
    const float* vW  = (const float*)d_in[19];
    const float* vb  = (const float*)d_in[20];

    const int nAgents = in_sizes[2];

    phaseR_kernel<<<20, 128>>>();
    phaseB_kernel<<<NBLK_B, 128>>>(z_curr, z_target,
                                   bW0, bb0, bs0, bB0,
                                   bW1, bb1, bs1, bB1, cW, cb);
    phaseT_kernel<<<NTAB / 8, 256>>>(tW0, tb0, tW1, tb1, cW,
                                     uW, ub, vW, vb);
    phaseI_kernel<<<(nAgents + 255) / 256, 256>>>(xi_curr,
                                                  (float*)d_out, nAgents);
}